// round 8
// baseline (speedup 1.0000x reference)
#include <cuda_runtime.h>
#include <cuda_bf16.h>
#include <cstdint>
#include <math.h>

#define BB 4
#define SS 4096
#define DD 1024
#define MM (BB * SS)   // 16384

// ---------------------------------------------------------------------------
// Scratch (__device__ globals; alloc-free rule)
// ---------------------------------------------------------------------------
__device__ __align__(256) __nv_bfloat16 g_xh[(size_t)MM * DD];
__device__ __align__(256) __nv_bfloat16 g_xl[(size_t)MM * DD];
__device__ __align__(256) __nv_bfloat16 g_wh[(size_t)3 * DD * DD];
__device__ __align__(256) __nv_bfloat16 g_wl[(size_t)3 * DD * DD];
__device__ __align__(256) __nv_bfloat16 g_qh[(size_t)MM * DD];
__device__ __align__(256) __nv_bfloat16 g_ql[(size_t)MM * DD];
__device__ __align__(256) __nv_bfloat16 g_kh[(size_t)MM * DD];
__device__ __align__(256) __nv_bfloat16 g_kl[(size_t)MM * DD];
__device__ __align__(256) __nv_bfloat16 g_vth[(size_t)MM * DD];  // [b][e][s]
__device__ __align__(256) __nv_bfloat16 g_vtl[(size_t)MM * DD];  // [b][e][s]
__device__ __align__(256) float         g_p [(size_t)BB * SS * SS]; // fp32 scores
__device__ __align__(256) __nv_bfloat16 g_ph[(size_t)BB * SS * SS]; // softmax hi
__device__ __align__(256) __nv_bfloat16 g_pl[(size_t)BB * SS * SS]; // softmax lo

// ---------------------------------------------------------------------------
// PTX helpers (sm_80-era PTX only: cp.async, ldmatrix, mma.sync)
// ---------------------------------------------------------------------------
__device__ __forceinline__ uint32_t smem_u32(const void* p) {
    uint32_t a;
    asm("{ .reg .u64 t; cvta.to.shared.u64 t, %1; cvt.u32.u64 %0, t; }"
        : "=r"(a) : "l"(p));
    return a;
}

#define LDSM4(r0, r1, r2, r3, addr) \
    asm volatile("ldmatrix.sync.aligned.m8n8.x4.shared.b16 {%0,%1,%2,%3}, [%4];" \
                 : "=r"(r0), "=r"(r1), "=r"(r2), "=r"(r3) : "r"(addr))

#define LDSM2(r0, r1, addr) \
    asm volatile("ldmatrix.sync.aligned.m8n8.x2.shared.b16 {%0,%1}, [%2];" \
                 : "=r"(r0), "=r"(r1) : "r"(addr))

__device__ __forceinline__ void mma_bf16(float* c, const uint32_t* a,
                                         uint32_t b0, uint32_t b1) {
    asm volatile(
        "mma.sync.aligned.m16n8k16.row.col.f32.bf16.bf16.f32 "
        "{%0,%1,%2,%3}, {%4,%5,%6,%7}, {%8,%9}, {%0,%1,%2,%3};"
        : "+f"(c[0]), "+f"(c[1]), "+f"(c[2]), "+f"(c[3])
        : "r"(a[0]), "r"(a[1]), "r"(a[2]), "r"(a[3]), "r"(b0), "r"(b1));
}

template <int N>
__device__ __forceinline__ void cp_wait() {
    asm volatile("cp.async.wait_group %0;" :: "n"(N) : "memory");
}
__device__ __forceinline__ void cp_commit() {
    asm volatile("cp.async.commit_group;" ::: "memory");
}

// ---------------------------------------------------------------------------
// smem stage: A (256x64 bf16 hi+lo) + B (128x64 bf16 hi+lo), 128B rows, SW128
// ---------------------------------------------------------------------------
#define T_AH     0
#define T_AL     32768
#define T_BH     65536
#define T_BL     81920
#define STAGE_SZ 98304
#define SMEM_BYTES (2 * STAGE_SZ)

__device__ __forceinline__ uint32_t sw_off(int r, int cbyte) {
    uint32_t off = (uint32_t)(r * 128 + cbyte);
    return off ^ ((off >> 3) & 0x70);
}

// 128-row x 64-bf16 tile via cp.async (4 x 16B per thread)
__device__ __forceinline__ void cp_tileB(uint32_t sdst,
                                         const __nv_bfloat16* __restrict__ g,
                                         size_t row0, int ldk, int k0) {
    const int t = threadIdx.x;
    const char* gb = (const char*)(g + row0 * (size_t)ldk + (size_t)k0);
    #pragma unroll
    for (int i = 0; i < 4; i++) {
        int u = t + i * 256;            // 0..1023
        int r = u >> 3, cb = (u & 7) * 16;
        const char* src = gb + (size_t)r * (size_t)ldk * 2 + cb;
        asm volatile("cp.async.cg.shared.global [%0], [%1], 16;"
                     :: "r"(sdst + sw_off(r, cb)), "l"(src) : "memory");
    }
}

// 256-row x 64-bf16 tile via cp.async (8 x 16B per thread)
__device__ __forceinline__ void cp_tileA(uint32_t sdst,
                                         const __nv_bfloat16* __restrict__ g,
                                         size_t row0, int ldk, int k0) {
    const int t = threadIdx.x;
    const char* gb = (const char*)(g + row0 * (size_t)ldk + (size_t)k0);
    #pragma unroll
    for (int i = 0; i < 8; i++) {
        int u = t + i * 256;            // 0..2047
        int r = u >> 3, cb = (u & 7) * 16;
        const char* src = gb + (size_t)r * (size_t)ldk * 2 + cb;
        asm volatile("cp.async.cg.shared.global [%0], [%1], 16;"
                     :: "r"(sdst + sw_off(r, cb)), "l"(src) : "memory");
    }
}

// ---------------------------------------------------------------------------
// One BK=64 chunk: C(256x128) += (Ah+Al)(256x64) @ (Bh+Bl)(128x64)^T, 3-pass.
// Warp grid 4x2, warp tile 64x64. C[am*8+bn][4].
// ---------------------------------------------------------------------------
__device__ __forceinline__ void compute_chunk(uint32_t stage, float C[32][4]) {
    const int lane = threadIdx.x & 31;
    const int wid  = threadIdx.x >> 5;
    const int wm = wid >> 1;  // 0..3: 64-row band
    const int wn = wid & 1;   // 0..1: 64-col band

    #pragma unroll
    for (int ks = 0; ks < 4; ks++) {
        uint32_t ah[4][4], al[4][4], bh[8][2], bl[8][2];
        #pragma unroll
        for (int am = 0; am < 4; am++) {
            int r  = wm * 64 + am * 16 + (lane & 15);
            int cb = ks * 32 + (lane >> 4) * 16;
            uint32_t o = sw_off(r, cb);
            LDSM4(ah[am][0], ah[am][1], ah[am][2], ah[am][3], stage + T_AH + o);
            LDSM4(al[am][0], al[am][1], al[am][2], al[am][3], stage + T_AL + o);
        }
        #pragma unroll
        for (int bn = 0; bn < 8; bn++) {
            int r  = wn * 64 + bn * 8 + (lane & 7);
            int cb = ks * 32 + ((lane >> 3) & 1) * 16;
            uint32_t o = sw_off(r, cb);
            LDSM2(bh[bn][0], bh[bn][1], stage + T_BH + o);
            LDSM2(bl[bn][0], bl[bn][1], stage + T_BL + o);
        }
        #pragma unroll
        for (int am = 0; am < 4; am++) {
            #pragma unroll
            for (int bn = 0; bn < 8; bn++) {
                float* c = C[am * 8 + bn];
                mma_bf16(c, ah[am], bh[bn][0], bh[bn][1]);
                mma_bf16(c, ah[am], bl[bn][0], bl[bn][1]);
                mma_bf16(c, al[am], bh[bn][0], bh[bn][1]);
            }
        }
    }
}

// ---------------------------------------------------------------------------
// 256x128 NT GEMM tile, 2-stage cp.async pipeline.
// ---------------------------------------------------------------------------
__device__ __forceinline__ void gemm_tile(
    char* smem,
    const __nv_bfloat16* __restrict__ Ah, const __nv_bfloat16* __restrict__ Al,
    size_t arow0, int lda,
    const __nv_bfloat16* __restrict__ Bh, const __nv_bfloat16* __restrict__ Bl,
    size_t brow0, int ldb,
    int nch, float C[32][4])
{
    const uint32_t sb = smem_u32(smem);

    #pragma unroll
    for (int i = 0; i < 32; i++)
        #pragma unroll
        for (int j = 0; j < 4; j++) C[i][j] = 0.0f;

    cp_tileA(sb + T_AH, Ah, arow0, lda, 0);
    cp_tileA(sb + T_AL, Al, arow0, lda, 0);
    cp_tileB(sb + T_BH, Bh, brow0, ldb, 0);
    cp_tileB(sb + T_BL, Bl, brow0, ldb, 0);
    cp_commit();

    for (int c = 0; c < nch; c++) {
        if (c + 1 < nch) {
            const uint32_t ns = sb + ((c + 1) & 1) * STAGE_SZ;
            const int k0 = (c + 1) * 64;
            cp_tileA(ns + T_AH, Ah, arow0, lda, k0);
            cp_tileA(ns + T_AL, Al, arow0, lda, k0);
            cp_tileB(ns + T_BH, Bh, brow0, ldb, k0);
            cp_tileB(ns + T_BL, Bl, brow0, ldb, k0);
            cp_commit();
            cp_wait<1>();
        } else {
            cp_wait<0>();
        }
        __syncthreads();
        compute_chunk(sb + (c & 1) * STAGE_SZ, C);
        __syncthreads();
    }
}

// C fragment coords: rows gr, gr+8; cols gc, gc+1
#define FRAG_COORDS() \
    const int lane = threadIdx.x & 31; \
    const int wid  = threadIdx.x >> 5; \
    const int wm = wid >> 1, wn = wid & 1;

// ---------------------------------------------------------------------------
// One merged split kernel: fp32 -> bf16 hi/lo for X, Wq, Wk, Wv
// ---------------------------------------------------------------------------
#define X4 ((MM * DD) / 4)
#define W4 ((DD * DD) / 4)

__global__ __launch_bounds__(256) void split_all_kernel(
    const float* __restrict__ X, const float* __restrict__ Wq,
    const float* __restrict__ Wk, const float* __restrict__ Wv)
{
    int i = blockIdx.x * 256 + threadIdx.x;
    const float* src;
    __nv_bfloat16 *h, *l;
    size_t off;
    if (i < X4) {
        src = X; h = g_xh; l = g_xl; off = (size_t)i;
    } else {
        int j = i - X4;
        if (j >= 3 * W4) return;
        int w = j / W4;
        off = (size_t)(j - w * W4);
        src = (w == 0) ? Wq : (w == 1) ? Wk : Wv;
        h = g_wh + (size_t)w * DD * DD;
        l = g_wl + (size_t)w * DD * DD;
    }
    float4 v = ((const float4*)src)[off];
    __nv_bfloat16 h0 = __float2bfloat16(v.x), h1 = __float2bfloat16(v.y);
    __nv_bfloat16 h2 = __float2bfloat16(v.z), h3 = __float2bfloat16(v.w);
    __nv_bfloat162 a, b;
    a.x = h0; a.y = h1; b.x = h2; b.y = h3;
    ((__nv_bfloat162*)h)[2 * off] = a; ((__nv_bfloat162*)h)[2 * off + 1] = b;
    a.x = __float2bfloat16(v.x - __bfloat162float(h0));
    a.y = __float2bfloat16(v.y - __bfloat162float(h1));
    b.x = __float2bfloat16(v.z - __bfloat162float(h2));
    b.y = __float2bfloat16(v.w - __bfloat162float(h3));
    ((__nv_bfloat162*)l)[2 * off] = a; ((__nv_bfloat162*)l)[2 * off + 1] = b;
}

// ---------------------------------------------------------------------------
// Projection: z=0 Q, z=1 K (bf16 hi/lo out), z=2 V (transposed via smem)
// ---------------------------------------------------------------------------
__global__ __launch_bounds__(256, 1) void proj_kernel()
{
    extern __shared__ char smem[];
    const int z = blockIdx.z;
    const size_t m0 = (size_t)blockIdx.x * 256;
    const int n0 = blockIdx.y * 128;

    float C[32][4];
    gemm_tile(smem,
              g_xh, g_xl, m0, DD,
              g_wh + (size_t)z * DD * DD, g_wl + (size_t)z * DD * DD, (size_t)n0, DD,
              DD / 64, C);

    FRAG_COORDS();
    if (z < 2) {
        __nv_bfloat16* H = (z == 0) ? g_qh : g_kh;
        __nv_bfloat16* L = (z == 0) ? g_ql : g_kl;
        #pragma unroll
        for (int am = 0; am < 4; am++) {
            #pragma unroll
            for (int bn = 0; bn < 8; bn++) {
                const float* c = C[am * 8 + bn];
                const int gr = wm * 64 + am * 16 + (lane >> 2);
                const int gc = n0 + wn * 64 + bn * 8 + (lane & 3) * 2;
                #pragma unroll
                for (int half = 0; half < 2; half++) {
                    float f0 = c[half * 2], f1 = c[half * 2 + 1];
                    __nv_bfloat16 h0 = __float2bfloat16(f0);
                    __nv_bfloat16 h1 = __float2bfloat16(f1);
                    __nv_bfloat162 hv, lv;
                    hv.x = h0; hv.y = h1;
                    lv.x = __float2bfloat16(f0 - __bfloat162float(h0));
                    lv.y = __float2bfloat16(f1 - __bfloat162float(h1));
                    size_t a = (m0 + (size_t)(gr + half * 8)) * DD + gc;
                    *(__nv_bfloat162*)(H + a) = hv;
                    *(__nv_bfloat162*)(L + a) = lv;
                }
            }
        }
    } else {
        // V: transpose 256x128 through smem -> coalesced bf16 stores along s
        float (*sf)[132] = (float (*)[132])smem;
        __syncthreads();  // GEMM stages dead; reuse (256*132*4 = 135KB < 192KB)
        #pragma unroll
        for (int am = 0; am < 4; am++) {
            #pragma unroll
            for (int bn = 0; bn < 8; bn++) {
                const float* c = C[am * 8 + bn];
                const int gr  = wm * 64 + am * 16 + (lane >> 2);
                const int gcl = wn * 64 + bn * 8 + (lane & 3) * 2;
                sf[gr][gcl]         = c[0];
                sf[gr][gcl + 1]     = c[1];
                sf[gr + 8][gcl]     = c[2];
                sf[gr + 8][gcl + 1] = c[3];
            }
        }
        __syncthreads();
        const int tid = threadIdx.x;
        const int e_l = tid >> 1;            // 0..127 local e column
        const int s0  = (tid & 1) * 128;     // half of the 256 s-rows
        const int b = (int)(m0 >> 12);
        const int sbase = (int)(m0 & (SS - 1));
        #pragma unroll
        for (int blk = 0; blk < 2; blk++) {
            __align__(16) unsigned short hb[64], lb[64];
            #pragma unroll
            for (int j = 0; j < 64; j++) {
                float f = sf[s0 + blk * 64 + j][e_l];
                __nv_bfloat16 hh = __float2bfloat16(f);
                __nv_bfloat16 ll = __float2bfloat16(f - __bfloat162float(hh));
                hb[j] = *(unsigned short*)&hh;
                lb[j] = *(unsigned short*)&ll;
            }
            size_t a = ((size_t)b * DD + n0 + e_l) * SS + sbase + s0 + blk * 64;
            #pragma unroll
            for (int v = 0; v < 8; v++) {
                *(uint4*)(g_vth + a + v * 8) = *(uint4*)&hb[v * 8];
                *(uint4*)(g_vtl + a + v * 8) = *(uint4*)&lb[v * 8];
            }
        }
    }
}

// ---------------------------------------------------------------------------
// Scores: P[b,q,k] = (Q.K)/32, causal tile skip (256-row q tiles)
// ---------------------------------------------------------------------------
__global__ __launch_bounds__(256, 1) void scores_kernel()
{
    if ((int)blockIdx.y > 2 * (int)blockIdx.x + 1) return;
    extern __shared__ char smem[];
    const int b = blockIdx.z;
    const size_t q0 = (size_t)blockIdx.x * 256;
    const size_t k0 = (size_t)blockIdx.y * 128;

    float C[32][4];
    gemm_tile(smem,
              g_qh + (size_t)b * SS * DD, g_ql + (size_t)b * SS * DD, q0, DD,
              g_kh + (size_t)b * SS * DD, g_kl + (size_t)b * SS * DD, k0, DD,
              DD / 64, C);

    FRAG_COORDS();
    float* P = g_p + (size_t)b * SS * SS;
    const float scale = 0.03125f;  // 1/sqrt(1024)
    #pragma unroll
    for (int am = 0; am < 4; am++) {
        #pragma unroll
        for (int bn = 0; bn < 8; bn++) {
            const float* c = C[am * 8 + bn];
            const int gr = wm * 64 + am * 16 + (lane >> 2);
            const int gc = (int)k0 + wn * 64 + bn * 8 + (lane & 3) * 2;
            float2 v0 = make_float2(c[0] * scale, c[1] * scale);
            float2 v1 = make_float2(c[2] * scale, c[3] * scale);
            *(float2*)(P + (q0 + (size_t)gr) * SS + gc) = v0;
            *(float2*)(P + (q0 + (size_t)gr + 8) * SS + gc) = v1;
        }
    }
}

// ---------------------------------------------------------------------------
// Softmax over k in [0,q]: online stats pass + write pass.
// Zero tail to the 256-tile edge (PV reads K up to that edge).
// ---------------------------------------------------------------------------
__global__ __launch_bounds__(256) void softmax_kernel()
{
    const int q = blockIdx.x;
    const int b = blockIdx.y;
    const size_t ro = (size_t)b * SS * SS + (size_t)q * SS;
    const float* row = g_p + ro;
    __nv_bfloat16* ph = g_ph + ro;
    __nv_bfloat16* pl = g_pl + ro;
    const int len = q + 1;
    const int kend = ((q >> 8) + 1) << 8;
    const int t = threadIdx.x;

    __shared__ float redm[256];
    __shared__ float reds[256];

    float m = -1e30f, s = 0.0f;
    for (int k = t; k < len; k += 256) {
        float x = row[k];
        if (x > m) { s = s * __expf(m - x) + 1.0f; m = x; }
        else       { s += __expf(x - m); }
    }
    redm[t] = m; reds[t] = s;
    __syncthreads();
    for (int st = 128; st > 0; st >>= 1) {
        if (t < st) {
            float m2 = redm[t + st], s2 = reds[t + st];
            float M = fmaxf(redm[t], m2);
            reds[t] = reds[t] * __expf(redm[t] - M) + s2 * __expf(m2 - M);
            redm[t] = M;
        }
        __syncthreads();
    }
    const float M = redm[0];
    const float inv = 1.0f / reds[0];

    for (int k = t; k < len; k += 256) {
        float w = __expf(row[k] - M) * inv;
        __nv_bfloat16 hh = __float2bfloat16(w);
        ph[k] = hh;
        pl[k] = __float2bfloat16(w - __bfloat162float(hh));
    }
    const __nv_bfloat16 z = __float2bfloat16(0.0f);
    for (int k = len + t; k < kend; k += 256) { ph[k] = z; pl[k] = z; }
}

// ---------------------------------------------------------------------------
// Output: O[b,q,e] = sum_k P[b,q,k] * Vt[b,e,k], K clamped to 256-tile edge.
// q-blocks processed heaviest-first (reversed blockIdx.x) for load balance.
// ---------------------------------------------------------------------------
__global__ __launch_bounds__(256, 1) void pv_kernel(float* __restrict__ out)
{
    extern __shared__ char smem[];
    const int b = blockIdx.z;
    const int qi = (int)gridDim.x - 1 - (int)blockIdx.x;  // heavy tiles first
    const size_t q0 = (size_t)qi * 256;
    const size_t e0 = (size_t)blockIdx.y * 128;
    const int nch = 4 * (qi + 1);   // K = q0+256 in 64-chunks

    float C[32][4];
    gemm_tile(smem,
              g_ph + (size_t)b * SS * SS, g_pl + (size_t)b * SS * SS, q0, SS,
              g_vth + (size_t)b * DD * SS, g_vtl + (size_t)b * DD * SS, e0, SS,
              nch, C);

    FRAG_COORDS();
    #pragma unroll
    for (int am = 0; am < 4; am++) {
        #pragma unroll
        for (int bn = 0; bn < 8; bn++) {
            const float* c = C[am * 8 + bn];
            const int gr = wm * 64 + am * 16 + (lane >> 2);
            const int gc = (int)e0 + wn * 64 + bn * 8 + (lane & 3) * 2;
            float2 v0 = make_float2(c[0], c[1]);
            float2 v1 = make_float2(c[2], c[3]);
            *(float2*)(out + ((size_t)b * SS + q0 + (size_t)gr) * DD + gc) = v0;
            *(float2*)(out + ((size_t)b * SS + q0 + (size_t)gr + 8) * DD + gc) = v1;
        }
    }
}

// ---------------------------------------------------------------------------
extern "C" void kernel_launch(void* const* d_in, const int* in_sizes, int n_in,
                              void* d_out, int out_size)
{
    const float* X  = (const float*)d_in[0];
    const float* Wq = (const float*)d_in[1];
    const float* Wk = (const float*)d_in[2];
    const float* Wv = (const float*)d_in[3];
    float* out      = (float*)d_out;

    static int attr_done = 0;
    if (!attr_done) {
        cudaFuncSetAttribute(proj_kernel,   cudaFuncAttributeMaxDynamicSharedMemorySize, SMEM_BYTES);
        cudaFuncSetAttribute(scores_kernel, cudaFuncAttributeMaxDynamicSharedMemorySize, SMEM_BYTES);
        cudaFuncSetAttribute(pv_kernel,     cudaFuncAttributeMaxDynamicSharedMemorySize, SMEM_BYTES);
        attr_done = 1;
    }

    {
        int total = X4 + 3 * W4;
        split_all_kernel<<<(total + 255) / 256, 256>>>(X, Wq, Wk, Wv);
    }

    dim3 g1(MM / 256, DD / 128, 3);
    proj_kernel<<<g1, 256, SMEM_BYTES>>>();

    dim3 g2(SS / 256, SS / 128, BB);
    scores_kernel<<<g2, 256, SMEM_BYTES>>>();

    dim3 g3(SS, BB);
    softmax_kernel<<<g3, 256>>>();

    dim3 g4(SS / 256, DD / 128, BB);
    pv_kernel<<<g4, 256, SMEM_BYTES>>>(out);
}

// round 12
// speedup vs baseline: 1.0396x; 1.0396x over previous
#include <cuda_runtime.h>
#include <cuda_bf16.h>
#include <cstdint>
#include <math.h>

#define BB 4
#define SS 4096
#define DD 1024
#define MM (BB * SS)   // 16384

// ---------------------------------------------------------------------------
// Scratch (__device__ globals; alloc-free rule)
// ---------------------------------------------------------------------------
__device__ __align__(256) __nv_bfloat16 g_xh[(size_t)MM * DD];
__device__ __align__(256) __nv_bfloat16 g_xl[(size_t)MM * DD];
__device__ __align__(256) __nv_bfloat16 g_wh[(size_t)3 * DD * DD];
__device__ __align__(256) __nv_bfloat16 g_wl[(size_t)3 * DD * DD];
__device__ __align__(256) __nv_bfloat16 g_qh[(size_t)MM * DD];
__device__ __align__(256) __nv_bfloat16 g_ql[(size_t)MM * DD];
__device__ __align__(256) __nv_bfloat16 g_kh[(size_t)MM * DD];
__device__ __align__(256) __nv_bfloat16 g_kl[(size_t)MM * DD];
__device__ __align__(256) __nv_bfloat16 g_vth[(size_t)MM * DD];  // [b][e][s]
__device__ __align__(256) __nv_bfloat16 g_vtl[(size_t)MM * DD];  // [b][e][s]
__device__ __align__(256) float         g_p [(size_t)BB * SS * SS]; // fp32 scores
__device__ __align__(256) __nv_bfloat16 g_ph[(size_t)BB * SS * SS]; // exp hi
__device__ __align__(256) __nv_bfloat16 g_pl[(size_t)BB * SS * SS]; // exp lo
__device__ __align__(256) float         g_inv[(size_t)BB * SS];     // 1/rowsum

// ---------------------------------------------------------------------------
// PTX helpers (sm_80-era PTX only: cp.async, ldmatrix, mma.sync)
// ---------------------------------------------------------------------------
__device__ __forceinline__ uint32_t smem_u32(const void* p) {
    uint32_t a;
    asm("{ .reg .u64 t; cvta.to.shared.u64 t, %1; cvt.u32.u64 %0, t; }"
        : "=r"(a) : "l"(p));
    return a;
}

#define LDSM4(r0, r1, r2, r3, addr) \
    asm volatile("ldmatrix.sync.aligned.m8n8.x4.shared.b16 {%0,%1,%2,%3}, [%4];" \
                 : "=r"(r0), "=r"(r1), "=r"(r2), "=r"(r3) : "r"(addr))

__device__ __forceinline__ void mma_bf16(float* c, const uint32_t* a,
                                         uint32_t b0, uint32_t b1) {
    asm volatile(
        "mma.sync.aligned.m16n8k16.row.col.f32.bf16.bf16.f32 "
        "{%0,%1,%2,%3}, {%4,%5,%6,%7}, {%8,%9}, {%0,%1,%2,%3};"
        : "+f"(c[0]), "+f"(c[1]), "+f"(c[2]), "+f"(c[3])
        : "r"(a[0]), "r"(a[1]), "r"(a[2]), "r"(a[3]), "r"(b0), "r"(b1));
}

template <int N>
__device__ __forceinline__ void cp_wait() {
    asm volatile("cp.async.wait_group %0;" :: "n"(N) : "memory");
}
__device__ __forceinline__ void cp_commit() {
    asm volatile("cp.async.commit_group;" ::: "memory");
}

// smem stage layout: 4 tiles of 128 rows x 64 bf16 (128B rows, SW128 swizzle)
#define T_AH     0
#define T_AL     16384
#define T_BH     32768
#define T_BL     49152
#define STAGE_SZ 65536
#define NSTAGE   3
#define SMEM_BYTES (NSTAGE * STAGE_SZ)

__device__ __forceinline__ uint32_t sw_off(int r, int cbyte) {
    uint32_t off = (uint32_t)(r * 128 + cbyte);
    return off ^ ((off >> 3) & 0x70);
}

// Load one 128x64-bf16 tile (K-contiguous source) into swizzled smem via cp.async.
__device__ __forceinline__ void cp_tile(uint32_t sdst,
                                        const __nv_bfloat16* __restrict__ g,
                                        size_t row0, int ldk, int k0) {
    const int t = threadIdx.x;
    const char* gb = (const char*)(g + row0 * (size_t)ldk + (size_t)k0);
    #pragma unroll
    for (int i = 0; i < 4; i++) {
        int u = t + i * 256;            // 0..1023
        int r = u >> 3, cb = (u & 7) * 16;
        const char* src = gb + (size_t)r * (size_t)ldk * 2 + cb;
        asm volatile("cp.async.cg.shared.global [%0], [%1], 16;"
                     :: "r"(sdst + sw_off(r, cb)), "l"(src) : "memory");
    }
}

// ---------------------------------------------------------------------------
// Compute one BK=64 chunk: C += (Ah+Al)(128x64) @ (Bh+Bl)(128x64)^T (3 passes)
// ---------------------------------------------------------------------------
__device__ __forceinline__ void compute_chunk(uint32_t stage, float C[16][4]) {
    const int lane = threadIdx.x & 31;
    const int wid  = threadIdx.x >> 5;
    const int wm = wid & 1;   // 0/1: 64-row half
    const int wn = wid >> 1;  // 0..3: 32-col quarter

    uint32_t ah[4][4], al[4][4], bh[4][4], bl[4][4];

    #pragma unroll
    for (int ks = 0; ks < 4; ks++) {
        if ((ks & 1) == 0) {
            #pragma unroll
            for (int n = 0; n < 4; n++) {
                int r  = wn * 32 + n * 8 + (lane & 7);
                int cb = ks * 32 + (lane >> 3) * 16;
                uint32_t o = sw_off(r, cb);
                LDSM4(bh[n][0], bh[n][1], bh[n][2], bh[n][3], stage + T_BH + o);
                LDSM4(bl[n][0], bl[n][1], bl[n][2], bl[n][3], stage + T_BL + o);
            }
        }
        #pragma unroll
        for (int am = 0; am < 4; am++) {
            int r  = wm * 64 + am * 16 + (lane & 15);
            int cb = ks * 32 + (lane >> 4) * 16;
            uint32_t o = sw_off(r, cb);
            LDSM4(ah[am][0], ah[am][1], ah[am][2], ah[am][3], stage + T_AH + o);
            LDSM4(al[am][0], al[am][1], al[am][2], al[am][3], stage + T_AL + o);
        }
        const int kp = (ks & 1) * 2;
        #pragma unroll
        for (int am = 0; am < 4; am++) {
            #pragma unroll
            for (int n = 0; n < 4; n++) {
                float* c = C[am * 4 + n];
                mma_bf16(c, ah[am], bh[n][kp], bh[n][kp + 1]);
                mma_bf16(c, ah[am], bl[n][kp], bl[n][kp + 1]);
                mma_bf16(c, al[am], bh[n][kp], bh[n][kp + 1]);
            }
        }
    }
}

// ---------------------------------------------------------------------------
// 128x128 NT GEMM tile: C = (Ah+Al)[128,K] @ (Bh+Bl)[128,K]^T, K = nch*64
// 3-stage cp.async pipeline, ONE __syncthreads per chunk.
// ---------------------------------------------------------------------------
__device__ __forceinline__ void gemm_tile(
    char* smem,
    const __nv_bfloat16* __restrict__ Ah, const __nv_bfloat16* __restrict__ Al,
    size_t arow0, int lda,
    const __nv_bfloat16* __restrict__ Bh, const __nv_bfloat16* __restrict__ Bl,
    size_t brow0, int ldb,
    int nch, float C[16][4])
{
    const uint32_t sb = smem_u32(smem);

    #pragma unroll
    for (int i = 0; i < 16; i++)
        #pragma unroll
        for (int j = 0; j < 4; j++) C[i][j] = 0.0f;

    // prologue: stages 0, 1  (nch >= 2 always)
    cp_tile(sb + T_AH, Ah, arow0, lda, 0);
    cp_tile(sb + T_AL, Al, arow0, lda, 0);
    cp_tile(sb + T_BH, Bh, brow0, ldb, 0);
    cp_tile(sb + T_BL, Bl, brow0, ldb, 0);
    cp_commit();
    {
        const uint32_t ns = sb + STAGE_SZ;
        cp_tile(ns + T_AH, Ah, arow0, lda, 64);
        cp_tile(ns + T_AL, Al, arow0, lda, 64);
        cp_tile(ns + T_BH, Bh, brow0, ldb, 64);
        cp_tile(ns + T_BL, Bl, brow0, ldb, 64);
        cp_commit();
    }

    int st = 0;        // stage index of chunk c
    int st2 = 2;       // stage index of chunk c+2
    for (int c = 0; c < nch; c++) {
        if (c == nch - 1) cp_wait<0>(); else cp_wait<1>();
        __syncthreads();
        if (c + 2 < nch) {
            const uint32_t ns = sb + st2 * STAGE_SZ;
            const int k0 = (c + 2) * 64;
            cp_tile(ns + T_AH, Ah, arow0, lda, k0);
            cp_tile(ns + T_AL, Al, arow0, lda, k0);
            cp_tile(ns + T_BH, Bh, brow0, ldb, k0);
            cp_tile(ns + T_BL, Bl, brow0, ldb, k0);
            cp_commit();
        }
        compute_chunk(sb + st * STAGE_SZ, C);
        st  = (st  == NSTAGE - 1) ? 0 : st  + 1;
        st2 = (st2 == NSTAGE - 1) ? 0 : st2 + 1;
    }
}

// C fragment coords: rows gr, gr+8; cols gc, gc+1
#define FRAG_COORDS() \
    const int lane = threadIdx.x & 31; \
    const int wid  = threadIdx.x >> 5; \
    const int wm = wid & 1, wn = wid >> 1;

// ---------------------------------------------------------------------------
// One merged split kernel: fp32 -> bf16 hi/lo for X, Wq, Wk, Wv
// ---------------------------------------------------------------------------
#define X4 ((MM * DD) / 4)
#define W4 ((DD * DD) / 4)

__global__ __launch_bounds__(256) void split_all_kernel(
    const float* __restrict__ X, const float* __restrict__ Wq,
    const float* __restrict__ Wk, const float* __restrict__ Wv)
{
    int i = blockIdx.x * 256 + threadIdx.x;
    const float* src;
    __nv_bfloat16 *h, *l;
    size_t off;
    if (i < X4) {
        src = X; h = g_xh; l = g_xl; off = (size_t)i;
    } else {
        int j = i - X4;
        if (j >= 3 * W4) return;
        int w = j / W4;
        off = (size_t)(j - w * W4);
        src = (w == 0) ? Wq : (w == 1) ? Wk : Wv;
        h = g_wh + (size_t)w * DD * DD;
        l = g_wl + (size_t)w * DD * DD;
    }
    float4 v = ((const float4*)src)[off];
    __nv_bfloat16 h0 = __float2bfloat16(v.x), h1 = __float2bfloat16(v.y);
    __nv_bfloat16 h2 = __float2bfloat16(v.z), h3 = __float2bfloat16(v.w);
    __nv_bfloat162 a, b;
    a.x = h0; a.y = h1; b.x = h2; b.y = h3;
    ((__nv_bfloat162*)h)[2 * off] = a; ((__nv_bfloat162*)h)[2 * off + 1] = b;
    a.x = __float2bfloat16(v.x - __bfloat162float(h0));
    a.y = __float2bfloat16(v.y - __bfloat162float(h1));
    b.x = __float2bfloat16(v.z - __bfloat162float(h2));
    b.y = __float2bfloat16(v.w - __bfloat162float(h3));
    ((__nv_bfloat162*)l)[2 * off] = a; ((__nv_bfloat162*)l)[2 * off + 1] = b;
}

// ---------------------------------------------------------------------------
// Projection: z=0 Q (scaled by 1/32), z=1 K, z=2 V (transposed via smem)
// ---------------------------------------------------------------------------
__global__ __launch_bounds__(256, 1) void proj_kernel()
{
    extern __shared__ char smem[];
    const int z = blockIdx.z;
    const size_t m0 = (size_t)blockIdx.x * 128;
    const int n0 = blockIdx.y * 128;

    float C[16][4];
    gemm_tile(smem,
              g_xh, g_xl, m0, DD,
              g_wh + (size_t)z * DD * DD, g_wl + (size_t)z * DD * DD, (size_t)n0, DD,
              DD / 64, C);

    FRAG_COORDS();
    if (z < 2) {
        __nv_bfloat16* H = (z == 0) ? g_qh : g_kh;
        __nv_bfloat16* L = (z == 0) ? g_ql : g_kl;
        const float qs = (z == 0) ? 0.03125f : 1.0f;   // fold 1/sqrt(1024) into Q
        #pragma unroll
        for (int am = 0; am < 4; am++) {
            #pragma unroll
            for (int n = 0; n < 4; n++) {
                const float* c = C[am * 4 + n];
                const int gr = wm * 64 + am * 16 + (lane >> 2);
                const int gc = n0 + wn * 32 + n * 8 + (lane & 3) * 2;
                #pragma unroll
                for (int half = 0; half < 2; half++) {
                    float f0 = c[half * 2] * qs, f1 = c[half * 2 + 1] * qs;
                    __nv_bfloat16 h0 = __float2bfloat16(f0);
                    __nv_bfloat16 h1 = __float2bfloat16(f1);
                    __nv_bfloat162 hv, lv;
                    hv.x = h0; hv.y = h1;
                    lv.x = __float2bfloat16(f0 - __bfloat162float(h0));
                    lv.y = __float2bfloat16(f1 - __bfloat162float(h1));
                    size_t a = (m0 + (size_t)(gr + half * 8)) * DD + gc;
                    *(__nv_bfloat162*)(H + a) = hv;
                    *(__nv_bfloat162*)(L + a) = lv;
                }
            }
        }
    } else {
        // V: transpose through smem -> coalesced bf16 stores along s
        float (*sf)[132] = (float (*)[132])smem;
        __syncthreads();  // GEMM smem stages are dead; reuse as fp32 tile
        #pragma unroll
        for (int am = 0; am < 4; am++) {
            #pragma unroll
            for (int n = 0; n < 4; n++) {
                const float* c = C[am * 4 + n];
                const int gr  = wm * 64 + am * 16 + (lane >> 2);
                const int gcl = wn * 32 + n * 8 + (lane & 3) * 2;
                sf[gr][gcl]         = c[0];
                sf[gr][gcl + 1]     = c[1];
                sf[gr + 8][gcl]     = c[2];
                sf[gr + 8][gcl + 1] = c[3];
            }
        }
        __syncthreads();
        const int tid = threadIdx.x;
        const int e_l = tid >> 1;            // 0..127 local e column
        const int s0  = (tid & 1) * 64;      // half of the 128 s-rows
        const int b = (int)(m0 >> 12);
        const int sbase = (int)(m0 & (SS - 1));
        __align__(16) unsigned short hb[64], lb[64];
        #pragma unroll
        for (int j = 0; j < 64; j++) {
            float f = sf[s0 + j][e_l];
            __nv_bfloat16 hh = __float2bfloat16(f);
            __nv_bfloat16 ll = __float2bfloat16(f - __bfloat162float(hh));
            hb[j] = *(unsigned short*)&hh;
            lb[j] = *(unsigned short*)&ll;
        }
        size_t a = ((size_t)b * DD + n0 + e_l) * SS + sbase + s0;
        #pragma unroll
        for (int v = 0; v < 8; v++) {
            *(uint4*)(g_vth + a + v * 8) = *(uint4*)&hb[v * 8];
            *(uint4*)(g_vtl + a + v * 8) = *(uint4*)&lb[v * 8];
        }
    }
}

// ---------------------------------------------------------------------------
// Scores: P[b,q,k] = Q.K (Q pre-scaled), causal tile skip
// ---------------------------------------------------------------------------
__global__ __launch_bounds__(256, 1) void scores_kernel()
{
    if (blockIdx.y > blockIdx.x) return;
    extern __shared__ char smem[];
    const int b = blockIdx.z;
    const size_t q0 = (size_t)blockIdx.x * 128;
    const size_t k0 = (size_t)blockIdx.y * 128;

    float C[16][4];
    gemm_tile(smem,
              g_qh + (size_t)b * SS * DD, g_ql + (size_t)b * SS * DD, q0, DD,
              g_kh + (size_t)b * SS * DD, g_kl + (size_t)b * SS * DD, k0, DD,
              DD / 64, C);

    FRAG_COORDS();
    float* P = g_p + (size_t)b * SS * SS;
    #pragma unroll
    for (int am = 0; am < 4; am++) {
        #pragma unroll
        for (int n = 0; n < 4; n++) {
            const float* c = C[am * 4 + n];
            const int gr = wm * 64 + am * 16 + (lane >> 2);
            const int gc = (int)k0 + wn * 32 + n * 8 + (lane & 3) * 2;
            float2 v0 = make_float2(c[0], c[1]);
            float2 v1 = make_float2(c[2], c[3]);
            *(float2*)(P + (q0 + (size_t)gr) * SS + gc) = v0;
            *(float2*)(P + (q0 + (size_t)gr + 8) * SS + gc) = v1;
        }
    }
}

// ---------------------------------------------------------------------------
// Softmax stats + unnormalized exp:
//   pass 1: row max (pure fmax). pass 2: e=exp(x-M), write bf16 hi/lo, sum.
//   g_inv[b,q] = 1/sum; normalization deferred to PV epilogue.
// ---------------------------------------------------------------------------
__global__ __launch_bounds__(256) void softmax_kernel()
{
    const int q = blockIdx.x;
    const int b = blockIdx.y;
    const size_t ro = (size_t)b * SS * SS + (size_t)q * SS;
    const float* row = g_p + ro;
    __nv_bfloat16* ph = g_ph + ro;
    __nv_bfloat16* pl = g_pl + ro;
    const int len = q + 1;
    const int kend = ((q >> 7) + 1) << 7;
    const int t = threadIdx.x;

    __shared__ float red[256];

    // pass 1: max only (no exp, no branch)
    float m = -1e30f;
    for (int k = t; k < len; k += 256) m = fmaxf(m, row[k]);
    red[t] = m; __syncthreads();
    for (int s = 128; s > 0; s >>= 1) {
        if (t < s) red[t] = fmaxf(red[t], red[t + s]);
        __syncthreads();
    }
    const float M = red[0];
    __syncthreads();

    // pass 2: exp once, write unnormalized e, accumulate sum
    float sum = 0.0f;
    for (int k = t; k < len; k += 256) {
        float e = __expf(row[k] - M);
        sum += e;
        __nv_bfloat16 hh = __float2bfloat16(e);
        ph[k] = hh;
        pl[k] = __float2bfloat16(e - __bfloat162float(hh));
    }
    const __nv_bfloat16 z = __float2bfloat16(0.0f);
    for (int k = len + t; k < kend; k += 256) { ph[k] = z; pl[k] = z; }

    red[t] = sum; __syncthreads();
    for (int s = 128; s > 0; s >>= 1) {
        if (t < s) red[t] += red[t + s];
        __syncthreads();
    }
    if (t == 0) g_inv[(size_t)b * SS + q] = 1.0f / red[0];
}

// ---------------------------------------------------------------------------
// Output: O[b,q,e] = inv[q] * sum_k E[b,q,k] * Vt[b,e,k]; heavy q-tiles first
// ---------------------------------------------------------------------------
__global__ __launch_bounds__(256, 1) void pv_kernel(float* __restrict__ out)
{
    extern __shared__ char smem[];
    const int b = blockIdx.z;
    const int qi = (int)gridDim.x - 1 - (int)blockIdx.x;  // heavy tiles first
    const size_t q0 = (size_t)qi * 128;
    const size_t e0 = (size_t)blockIdx.y * 128;
    const int nch = 2 * (qi + 1);   // K = q0+128 in 64-chunks

    float C[16][4];
    gemm_tile(smem,
              g_ph + (size_t)b * SS * SS, g_pl + (size_t)b * SS * SS, q0, SS,
              g_vth + (size_t)b * DD * SS, g_vtl + (size_t)b * DD * SS, e0, SS,
              nch, C);

    FRAG_COORDS();
    const float* inv = g_inv + (size_t)b * SS + q0;
    #pragma unroll
    for (int am = 0; am < 4; am++) {
        const int gr = wm * 64 + am * 16 + (lane >> 2);
        const float i0 = inv[gr];
        const float i1 = inv[gr + 8];
        #pragma unroll
        for (int n = 0; n < 4; n++) {
            const float* c = C[am * 4 + n];
            const int gc = (int)e0 + wn * 32 + n * 8 + (lane & 3) * 2;
            float2 v0 = make_float2(c[0] * i0, c[1] * i0);
            float2 v1 = make_float2(c[2] * i1, c[3] * i1);
            *(float2*)(out + ((size_t)b * SS + q0 + (size_t)gr) * DD + gc) = v0;
            *(float2*)(out + ((size_t)b * SS + q0 + (size_t)gr + 8) * DD + gc) = v1;
        }
    }
}

// ---------------------------------------------------------------------------
extern "C" void kernel_launch(void* const* d_in, const int* in_sizes, int n_in,
                              void* d_out, int out_size)
{
    const float* X  = (const float*)d_in[0];
    const float* Wq = (const float*)d_in[1];
    const float* Wk = (const float*)d_in[2];
    const float* Wv = (const float*)d_in[3];
    float* out      = (float*)d_out;

    static int attr_done = 0;
    if (!attr_done) {
        cudaFuncSetAttribute(proj_kernel,   cudaFuncAttributeMaxDynamicSharedMemorySize, SMEM_BYTES);
        cudaFuncSetAttribute(scores_kernel, cudaFuncAttributeMaxDynamicSharedMemorySize, SMEM_BYTES);
        cudaFuncSetAttribute(pv_kernel,     cudaFuncAttributeMaxDynamicSharedMemorySize, SMEM_BYTES);
        attr_done = 1;
    }

    {
        int total = X4 + 3 * W4;
        split_all_kernel<<<(total + 255) / 256, 256>>>(X, Wq, Wk, Wv);
    }

    dim3 g1(MM / 128, DD / 128, 3);
    proj_kernel<<<g1, 256, SMEM_BYTES>>>();

    dim3 g2(SS / 128, SS / 128, BB);
    scores_kernel<<<g2, 256, SMEM_BYTES>>>();

    dim3 g3(SS, BB);
    softmax_kernel<<<g3, 256>>>();

    dim3 g4(SS / 128, DD / 128, BB);
    pv_kernel<<<g4, 256, SMEM_BYTES>>>(out);
}